// round 14
// baseline (speedup 1.0000x reference)
#include <cuda_runtime.h>
#include <cuda_bf16.h>

// CoverageLoss, fused single-kernel, fully closed form (no boundary read).
//
// Boundary samples are 4 axis-aligned uniform segments of the box with
// parallel coordinate lins[j] ~= j/99 (1-ulp exact). Min over an edge
// separates: (perp)^2 + min_j (par - j*w/99)^2 with j = clamp(round(t*99)).
//
// R14: 64 blocks x 512 threads; thread = (box, 4 points) -- same per-thread
// work as the proven layout, half the blocks (half the tail population).
// Block partial reduced by warp 0 in parallel (32 lanes <-> 32 pair-min
// values) instead of thread 0's serial 32-iteration loop.
// Tail: one contended atomicAdd(g_sum)+counter per block; last block writes
// out and resets scratch (graph-replay safe).

#define NPTS    2048
#define NBOX    64
#define PPTH    4                     // points per thread
#define NSLOT   8                     // point-slots per block (512 thr / 64 boxes)
#define PTSBLK  (NSLOT * PPTH)        // 32 points per block
#define NBLK    (NPTS / PTSBLK)       // 64 blocks
#define NLIN    100

__device__ float        g_sum = 0.0f;   // static zero-init; reset by last block
__device__ unsigned int g_cnt = 0u;

__global__ __launch_bounds__(512)
void cl_fused_kernel(const float* __restrict__ pred,
                     const float* __restrict__ frag,
                     float* __restrict__ out) {
    __shared__ float s_red[16][PPTH];   // one row per warp

    const int tid = threadIdx.x;
    const int b   = tid & 63;         // box index
    const int pl  = tid >> 6;         // point-slot 0..7 (two warps per slot)

    // ---- box constants (hoisted across 4 points, incl. both MUFU rcp) ----
    const float4 pr = ((const float4*)pred)[b];
    const float lx = pr.x, ly = pr.y, hx = pr.z, hy = pr.w;
    const float wx = hx - lx;
    const float wy = hy - ly;
    const float ex = wx + lx;          // right-edge x as the reference computes it
    const float ey = wy + ly;          // top-edge y
    const float c99rwx = 99.0f * __frcp_rn(wx);
    const float c99rwy = 99.0f * __frcp_rn(wy);
    const float wx99 = wx * (1.0f / 99.0f);   // grid step along x
    const float wy99 = wy * (1.0f / 99.0f);   // grid step along y

    // ---- 4 fragment points, contiguous: 2x float4 loads ----
    const int pbase = blockIdx.x * PTSBLK + pl * PPTH;
    const float4 f01 = ((const float4*)frag)[pbase / 2];
    const float4 f23 = ((const float4*)frag)[pbase / 2 + 1];
    float fxs[PPTH] = {f01.x, f01.z, f23.x, f23.z};
    float fys[PPTH] = {f01.y, f01.w, f23.y, f23.w};

    float vals[PPTH];
#pragma unroll
    for (int i = 0; i < PPTH; i++) {
        const float fx = fxs[i], fy = fys[i];
        const bool inside = (fx >= lx) && (fy >= ly) && (hx >= fx) && (hy >= fy);

        // vertical edges: x fixed, nearest y sample (F2I of NaN -> 0, clamp safe)
        const float dyl = fy - ly;
        const int j = min(max(__float2int_rn(dyl * c99rwy), 0), NLIN - 1);
        float d = fmaf((float)-j, wy99, dyl);     // fy - (ly + j*wy/99)
        const float mdy2 = d * d;
        const float dxl = fx - lx;
        const float dxh = fx - ex;
        const float dvert = fminf(dxl * dxl, dxh * dxh) + mdy2;

        // horizontal edges: y fixed, nearest x sample
        const int k = min(max(__float2int_rn(dxl * c99rwx), 0), NLIN - 1);
        d = fmaf((float)-k, wx99, dxl);           // fx - (lx + k*wx/99)
        const float mdx2 = d * d;
        const float dyh = fy - ey;
        const float dhorz = fminf(dyl * dyl, dyh * dyh) + mdx2;

        vals[i] = inside ? 0.0f : fminf(dvert, dhorz);
    }

    // ---- min over 64 boxes: shuffle within warp (32 boxes), pair via shared ----
#pragma unroll
    for (int o = 16; o > 0; o >>= 1) {
#pragma unroll
        for (int i = 0; i < PPTH; i++)
            vals[i] = fminf(vals[i], __shfl_xor_sync(0xffffffffu, vals[i], o));
    }
    if ((tid & 31) == 0) {
        const int w = tid >> 5;
#pragma unroll
        for (int i = 0; i < PPTH; i++) s_red[w][i] = vals[i];
    }
    __syncthreads();

    // ---- tail: warp 0 parallel pair-min + sum, then atomics; last-block finale ----
    if (tid < 32) {
        const int s = tid >> 2;        // slot 0..7
        const int i = tid & 3;         // point 0..3
        // min over the slot's two warps (boxes 0..31 vs 32..63)
        float v = fminf(s_red[2 * s][i], s_red[2 * s + 1][i]);
#pragma unroll
        for (int o = 16; o > 0; o >>= 1)
            v += __shfl_xor_sync(0xffffffffu, v, o);

        unsigned done = 0;
        if (tid == 0) {
            atomicAdd(&g_sum, v);
            __threadfence();
            done = atomicAdd(&g_cnt, 1u);
        }
        done = __shfl_sync(0xffffffffu, done, 0);
        if (done == NBLK - 1 && tid == 0) {
            float tot = atomicAdd(&g_sum, 0.0f);   // atomic read-back
            out[0] = tot * (1.0f / 64.0f);         // / FP
            g_sum = 0.0f;                          // restore invariant for replay
            g_cnt = 0u;
        }
    }
}

extern "C" void kernel_launch(void* const* d_in, const int* in_sizes, int n_in,
                              void* d_out, int out_size) {
    const float* pred = (const float*)d_in[0];   // [64,4]
    const float* frag = (const float*)d_in[1];   // [32,64,2]
    cl_fused_kernel<<<NBLK, 512>>>(pred, frag, (float*)d_out);
}

// round 15
// speedup vs baseline: 1.2126x; 1.2126x over previous
#include <cuda_runtime.h>
#include <cuda_bf16.h>

// CoverageLoss, fused single-kernel, fully closed form (no boundary read).
//
// Boundary samples are 4 axis-aligned uniform segments of the box with
// parallel coordinate lins[j] = linspace(0,1,100)[j] ~= j/99 (1-ulp exact).
// min over an edge separates: (perp)^2 + min_j (par - j*w/99)^2 with
// j = clamp(round(t*99), 0, 99)  ->  one F2I + one FFMA, no table, so the
// boundary tensor is never loaded (no cold DRAM fetch, no entry barrier).
//
// Final converged configuration (measured optimum across R7-R14):
//   - 128 blocks x 256 threads, thread = (box, 4 points), single wave
//     (beat 512x256, 32x256xPPTH16, 64x512)
//   - min over 64 boxes: warp shuffle (32) + one smem pair exchange
//   - tail: thread-0 serial pair-min/sum + contended atomicAdd(g_sum) +
//     counter; last block writes out and resets scratch (graph-replay safe)
//     (beat slot-STG tails and warp-parallel finales)

#define NPTS  2048
#define NBOX  64
#define PPTH  4                       // points per thread
#define NBLK  (NPTS / (PPTH * 4))     // 128 blocks, 16 points per block
#define NLIN  100

__device__ float        g_sum = 0.0f;   // static zero-init; reset by last block
__device__ unsigned int g_cnt = 0u;

__global__ __launch_bounds__(256)
void cl_fused_kernel(const float* __restrict__ pred,
                     const float* __restrict__ frag,
                     float* __restrict__ out) {
    __shared__ float s_red[8][PPTH];

    const int tid = threadIdx.x;
    const int b   = tid & 63;         // box index
    const int pl  = tid >> 6;         // point-slot 0..3 (two warps per slot)

    // ---- box constants (hoisted across 4 points, incl. both MUFU rcp) ----
    const float4 pr = ((const float4*)pred)[b];
    const float lx = pr.x, ly = pr.y, hx = pr.z, hy = pr.w;
    const float wx = hx - lx;
    const float wy = hy - ly;
    const float ex = wx + lx;          // right-edge x as the reference computes it
    const float ey = wy + ly;          // top-edge y
    const float c99rwx = 99.0f * __frcp_rn(wx);
    const float c99rwy = 99.0f * __frcp_rn(wy);
    const float wx99 = wx * (1.0f / 99.0f);   // grid step along x
    const float wy99 = wy * (1.0f / 99.0f);   // grid step along y

    // ---- 4 fragment points, contiguous: 2x float4 loads ----
    const int pbase = blockIdx.x * 16 + pl * PPTH;
    const float4 f01 = ((const float4*)frag)[pbase / 2];
    const float4 f23 = ((const float4*)frag)[pbase / 2 + 1];
    float fxs[PPTH] = {f01.x, f01.z, f23.x, f23.z};
    float fys[PPTH] = {f01.y, f01.w, f23.y, f23.w};

    float vals[PPTH];
#pragma unroll
    for (int i = 0; i < PPTH; i++) {
        const float fx = fxs[i], fy = fys[i];
        const bool inside = (fx >= lx) && (fy >= ly) && (hx >= fx) && (hy >= fy);

        // vertical edges: x fixed, nearest y sample (F2I of NaN -> 0, clamp safe)
        const float dyl = fy - ly;
        const int j = min(max(__float2int_rn(dyl * c99rwy), 0), NLIN - 1);
        float d = fmaf((float)-j, wy99, dyl);     // fy - (ly + j*wy/99)
        const float mdy2 = d * d;
        const float dxl = fx - lx;
        const float dxh = fx - ex;
        const float dvert = fminf(dxl * dxl, dxh * dxh) + mdy2;

        // horizontal edges: y fixed, nearest x sample
        const int k = min(max(__float2int_rn(dxl * c99rwx), 0), NLIN - 1);
        d = fmaf((float)-k, wx99, dxl);           // fx - (lx + k*wx/99)
        const float mdx2 = d * d;
        const float dyh = fy - ey;
        const float dhorz = fminf(dyl * dyl, dyh * dyh) + mdx2;

        vals[i] = inside ? 0.0f : fminf(dvert, dhorz);
    }

    // ---- min over 64 boxes: shuffle within warp (32 boxes), pair via shared ----
#pragma unroll
    for (int o = 16; o > 0; o >>= 1) {
#pragma unroll
        for (int i = 0; i < PPTH; i++)
            vals[i] = fminf(vals[i], __shfl_xor_sync(0xffffffffu, vals[i], o));
    }
    if ((tid & 31) == 0) {
        const int w = tid >> 5;
#pragma unroll
        for (int i = 0; i < PPTH; i++) s_red[w][i] = vals[i];
    }
    __syncthreads();

    // ---- tail (R8-proven): contended atomicAdd + counter, serial finale ----
    if (tid == 0) {
        float s = 0.0f;
#pragma unroll
        for (int p = 0; p < 4; p++)
#pragma unroll
            for (int i = 0; i < PPTH; i++)
                s += fminf(s_red[2 * p][i], s_red[2 * p + 1][i]);
        atomicAdd(&g_sum, s);
        __threadfence();
        unsigned done = atomicAdd(&g_cnt, 1u);
        if (done == NBLK - 1) {
            float tot = atomicAdd(&g_sum, 0.0f);   // atomic read-back
            out[0] = tot * (1.0f / 64.0f);         // / FP
            g_sum = 0.0f;                          // restore invariant for replay
            g_cnt = 0u;
        }
    }
}

extern "C" void kernel_launch(void* const* d_in, const int* in_sizes, int n_in,
                              void* d_out, int out_size) {
    const float* pred = (const float*)d_in[0];   // [64,4]
    const float* frag = (const float*)d_in[1];   // [32,64,2]
    cl_fused_kernel<<<NBLK, 256>>>(pred, frag, (float*)d_out);
}